// round 5
// baseline (speedup 1.0000x reference)
#include <cuda_runtime.h>
#include <cuda_bf16.h>
#include <math.h>
#include <stdint.h>

// ---------------- problem constants ----------------
#define BATCH   4
#define TLEN    2048
#define DMODEL  256
#define NSC     3
#define DM2     512
#define DIN     1024
#define NH      16
#define HD      64
#define DS      128
#define DPROJ   2320     // 2*DIN + 2*DS + NH
#define CCH     1280     // DIN + 2*DS
#define MROWS   (BATCH*TLEN)   // 8192

// ---------------- scratch (device globals; no allocation allowed) ----------------
__device__ float g_xg [(size_t)MROWS*768];
__device__ float g_xp [(size_t)MROWS*DMODEL];
__device__ float g_pre[(size_t)MROWS*DM2];
__device__ float g_h  [(size_t)MROWS*DM2];
__device__ float g_hf [(size_t)MROWS*DM2];
__device__ float g_zx [2][(size_t)MROWS*DPROJ];
__device__ float g_xbc[2][(size_t)MROWS*CCH];
__device__ float g_dt [2][(size_t)MROWS*NH];
__device__ float g_dA [2][(size_t)MROWS*NH];
__device__ float g_y  [2][(size_t)MROWS*DIN];
__device__ float g_od [2][(size_t)MROWS*DM2];
__device__ float g_u  [(size_t)MROWS*DM2];
__device__ float g_v  [(size_t)MROWS*DMODEL];
__device__ float g_fn [(size_t)MROWS*DMODEL];

// ---------------- helpers ----------------
__device__ __forceinline__ float siluf(float x) { return x / (1.f + __expf(-x)); }

__device__ __forceinline__ void mma_bf16(float c[4], const uint32_t a[4], const uint32_t b[2]) {
    asm volatile("mma.sync.aligned.m16n8k16.row.col.f32.bf16.bf16.f32 "
        "{%0,%1,%2,%3}, {%4,%5,%6,%7}, {%8,%9}, {%0,%1,%2,%3};"
        : "+f"(c[0]), "+f"(c[1]), "+f"(c[2]), "+f"(c[3])
        : "r"(a[0]), "r"(a[1]), "r"(a[2]), "r"(a[3]), "r"(b[0]), "r"(b[1]));
}

// split two floats into packed bf16 hi-word and lo-word (low 16 bits = first arg)
__device__ __forceinline__ void pksplit(float a, float b, uint32_t& h, uint32_t& l) {
    __nv_bfloat16 ha = __float2bfloat16(a), hb = __float2bfloat16(b);
    float ra = a - __bfloat162float(ha);
    float rb = b - __bfloat162float(hb);
    __nv_bfloat162 hh; hh.x = ha; hh.y = hb;
    __nv_bfloat162 ll; ll.x = __float2bfloat16(ra); ll.y = __float2bfloat16(rb);
    h = *(uint32_t*)&hh; l = *(uint32_t*)&ll;
}

// packed f32x2 ops (sm_103a FFMA2 path; only reachable via PTX)
#define FMA2(d, a, b, c) asm("fma.rn.f32x2 %0, %1, %2, %3;" : "=d"(d) : "d"(a), "d"(b), "d"(c))
#define MUL2(d, a, b)    asm("mul.rn.f32x2 %0, %1, %2;"     : "=d"(d) : "d"(a), "d"(b))
#define PACK2(d, lo, hi) asm("mov.b64 %0, {%1, %2};"        : "=d"(d) : "f"(lo), "f"(hi))
#define UNPACK2(lo, hi, s) asm("mov.b64 {%0, %1}, %2;"      : "=f"(lo), "=f"(hi) : "d"(s))

__device__ __forceinline__ float block_reduce(float v) {
    __shared__ float sb[33];
    int lane = threadIdx.x & 31, w = threadIdx.x >> 5;
    #pragma unroll
    for (int o = 16; o; o >>= 1) v += __shfl_xor_sync(0xffffffffu, v, o);
    __syncthreads();
    if (lane == 0) sb[w] = v;
    __syncthreads();
    int nw = blockDim.x >> 5;
    float r = (threadIdx.x < nw) ? sb[threadIdx.x] : 0.f;
    if (w == 0) {
        #pragma unroll
        for (int o = 8; o; o >>= 1) r += __shfl_xor_sync(0xffffffffu, r, o);
        if (lane == 0) sb[32] = r;
    }
    __syncthreads();
    return sb[32];
}

// ---------------- split-bf16 tensor-core GEMM (~17 mantissa bits) ----------------
// C[M,N] = A[M,K] @ op(B) (+bias).  x = hi + lo (bf16 each); hi*hi + hi*lo + lo*hi.
// TRANSB=false: B is [K,N] row-major.  TRANSB=true: B is [N,K] row-major.
// Block tile 128x128, BK=16, 256 threads (8 warps = 2Mx4N of 64x32 warp tiles).
// M % 128 == 0, K % 16 == 0; N guarded (N % 4 == 0).
#define ASTRW   1536    // A planes: [128 rows][pitch 12]
#define BSTRW_T 1536    // TRANSB B: same layout as A
#define BSTRW_N 1088    // !TRANSB B: [8 kp][pitch 136]  (136 -> conflict-free frag loads)

template<bool TRANSB>
__global__ void __launch_bounds__(256) tgemm(
    const float* __restrict__ A, const float* __restrict__ B,
    const float* __restrict__ bias, float* __restrict__ C,
    int M, int N, int K, size_t sA, size_t sB, size_t sC)
{
    A += (size_t)blockIdx.z * sA;
    B += (size_t)blockIdx.z * sB;
    C += (size_t)blockIdx.z * sC;

    extern __shared__ uint32_t sm[];
    constexpr int BSTRW = TRANSB ? BSTRW_T : BSTRW_N;
    uint32_t* As = sm;                 // 4 planes: (buf*2 + hl)*ASTRW
    uint32_t* Bs = sm + 4*ASTRW;       // 4 planes: (buf*2 + hl)*BSTRW

    const int tid = threadIdx.x;
    const int m0 = blockIdx.y * 128, n0 = blockIdx.x * 128;
    const int lane = tid & 31, w = tid >> 5;
    const int wm = (w & 1) * 64, wn = (w >> 1) * 32;
    const int g = lane >> 2, tq = lane & 3;

    float acc[4][4][4];
    #pragma unroll
    for (int i = 0; i < 4; i++)
        #pragma unroll
        for (int j = 0; j < 4; j++)
            #pragma unroll
            for (int q = 0; q < 4; q++) acc[i][j][q] = 0.f;

    const int aRow = tid >> 1;
    const int aK   = (tid & 1) * 8;
    const int bKp = tid >> 5;
    const int bN  = (tid & 31) * 4;

    float4 ra[2], rb[2];

    auto loadG = [&](int kc) {
        const float* Ar = A + (size_t)(m0 + aRow)*K + kc + aK;
        ra[0] = *(const float4*)(Ar);
        ra[1] = *(const float4*)(Ar + 4);
        if (TRANSB) {
            const float* Br = B + (size_t)(n0 + aRow)*K + kc + aK;
            rb[0] = *(const float4*)(Br);
            rb[1] = *(const float4*)(Br + 4);
        } else {
            if (n0 + bN < N) {
                rb[0] = *(const float4*)(B + (size_t)(kc + 2*bKp    )*N + n0 + bN);
                rb[1] = *(const float4*)(B + (size_t)(kc + 2*bKp + 1)*N + n0 + bN);
            } else {
                rb[0] = make_float4(0.f,0.f,0.f,0.f);
                rb[1] = make_float4(0.f,0.f,0.f,0.f);
            }
        }
    };
    auto storeS = [&](int buf) {
        uint32_t* ah = As + (buf*2    )*ASTRW;
        uint32_t* al = As + (buf*2 + 1)*ASTRW;
        uint32_t* bh = Bs + (buf*2    )*BSTRW;
        uint32_t* bl = Bs + (buf*2 + 1)*BSTRW;
        uint4 h4, l4;
        pksplit(ra[0].x, ra[0].y, h4.x, l4.x);
        pksplit(ra[0].z, ra[0].w, h4.y, l4.y);
        pksplit(ra[1].x, ra[1].y, h4.z, l4.z);
        pksplit(ra[1].z, ra[1].w, h4.w, l4.w);
        *(uint4*)(ah + aRow*12 + aK/2) = h4;
        *(uint4*)(al + aRow*12 + aK/2) = l4;
        if (TRANSB) {
            pksplit(rb[0].x, rb[0].y, h4.x, l4.x);
            pksplit(rb[0].z, rb[0].w, h4.y, l4.y);
            pksplit(rb[1].x, rb[1].y, h4.z, l4.z);
            pksplit(rb[1].z, rb[1].w, h4.w, l4.w);
            *(uint4*)(bh + aRow*12 + aK/2) = h4;
            *(uint4*)(bl + aRow*12 + aK/2) = l4;
        } else {
            pksplit(rb[0].x, rb[1].x, h4.x, l4.x);
            pksplit(rb[0].y, rb[1].y, h4.y, l4.y);
            pksplit(rb[0].z, rb[1].z, h4.z, l4.z);
            pksplit(rb[0].w, rb[1].w, h4.w, l4.w);
            *(uint4*)(bh + bKp*136 + bN) = h4;
            *(uint4*)(bl + bKp*136 + bN) = l4;
        }
    };

    loadG(0); storeS(0); __syncthreads();
    const int nCh = K >> 4;
    for (int c = 0; c < nCh; c++) {
        int buf = c & 1;
        if (c + 1 < nCh) loadG((c + 1) << 4);
        const uint32_t* ah = As + (buf*2    )*ASTRW;
        const uint32_t* al = As + (buf*2 + 1)*ASTRW;
        const uint32_t* bh = Bs + (buf*2    )*BSTRW;
        const uint32_t* bl = Bs + (buf*2 + 1)*BSTRW;

        uint32_t afh[4][4], afl[4][4], bfh[4][2], bfl[4][2];
        #pragma unroll
        for (int mi = 0; mi < 4; mi++) {
            int mr = wm + mi*16 + g;
            int i0 =  mr     *12 + tq;
            int i1 = (mr + 8)*12 + tq;
            afh[mi][0] = ah[i0];     afh[mi][1] = ah[i1];
            afh[mi][2] = ah[i0 + 4]; afh[mi][3] = ah[i1 + 4];
            afl[mi][0] = al[i0];     afl[mi][1] = al[i1];
            afl[mi][2] = al[i0 + 4]; afl[mi][3] = al[i1 + 4];
        }
        #pragma unroll
        for (int ni = 0; ni < 4; ni++) {
            int nc = wn + ni*8 + g;
            if (TRANSB) {
                int i0 = nc*12 + tq;
                bfh[ni][0] = bh[i0]; bfh[ni][1] = bh[i0 + 4];
                bfl[ni][0] = bl[i0]; bfl[ni][1] = bl[i0 + 4];
            } else {
                int i0 =  tq     *136 + nc;
                int i1 = (tq + 4)*136 + nc;
                bfh[ni][0] = bh[i0]; bfh[ni][1] = bh[i1];
                bfl[ni][0] = bl[i0]; bfl[ni][1] = bl[i1];
            }
        }
        #pragma unroll
        for (int mi = 0; mi < 4; mi++)
            #pragma unroll
            for (int ni = 0; ni < 4; ni++) {
                mma_bf16(acc[mi][ni], afh[mi], bfh[ni]);
                mma_bf16(acc[mi][ni], afh[mi], bfl[ni]);
                mma_bf16(acc[mi][ni], afl[mi], bfh[ni]);
            }
        if (c + 1 < nCh) { __syncthreads(); storeS(buf ^ 1); __syncthreads(); }
    }

    #pragma unroll
    for (int mi = 0; mi < 4; mi++) {
        int row = m0 + wm + mi*16 + g;
        #pragma unroll
        for (int ni = 0; ni < 4; ni++) {
            int col = n0 + wn + ni*8 + tq*2;
            if (col < N) {
                float b0v = bias ? bias[col]     : 0.f;
                float b1v = bias ? bias[col + 1] : 0.f;
                float2 v0; v0.x = acc[mi][ni][0] + b0v; v0.y = acc[mi][ni][1] + b1v;
                float2 v1; v1.x = acc[mi][ni][2] + b0v; v1.y = acc[mi][ni][3] + b1v;
                *(float2*)(C + (size_t)row*N + col)       = v0;
                *(float2*)(C + (size_t)(row + 8)*N + col) = v1;
            }
        }
    }
}

#define SMEM_NT ((4*ASTRW + 4*BSTRW_N)*4)   // 41984 bytes
#define SMEM_T  ((4*ASTRW + 4*BSTRW_T)*4)   // 49152 bytes

// ---------------- elementwise kernels ----------------
__global__ void gather_kernel(const float* __restrict__ x) {
    size_t idx = (size_t)blockIdx.x * blockDim.x + threadIdx.x;  // MROWS*768 exact
    size_t bt = idx / 768; int r = (int)(idx % 768);
    int s = r >> 8, d = r & 255;
    int b = (int)(bt >> 11), t = (int)(bt & 2047);
    g_xg[idx] = x[(((size_t)(b*NSC + s)*TLEN + t) << 8) + d];
}

__global__ void flip_kernel() {
    size_t idx = (size_t)blockIdx.x * blockDim.x + threadIdx.x;  // MROWS*512
    size_t bt = idx >> 9; int j = (int)(idx & 511);
    int b = (int)(bt >> 11), t = (int)(bt & 2047);
    g_hf[idx] = g_h[(((size_t)(b << 11) | (2047 - t)) << 9) | j];
}

__global__ void ln512_kernel(const float* __restrict__ in, const float* __restrict__ g,
                             const float* __restrict__ b, float* __restrict__ out) {
    int row = blockIdx.x, tid = threadIdx.x;
    const float* xr = in + (size_t)row * DM2;
    float v0 = xr[tid], v1 = xr[tid + 256];
    float mu = block_reduce(v0 + v1) * (1.f / 512.f);
    float d0 = v0 - mu, d1 = v1 - mu;
    float var = block_reduce(d0*d0 + d1*d1) * (1.f / 512.f);
    float inv = rsqrtf(var + 1e-5f);
    out[(size_t)row*DM2 + tid]       = d0 * inv * g[tid]       + b[tid];
    out[(size_t)row*DM2 + tid + 256] = d1 * inv * g[tid + 256] + b[tid + 256];
}

__global__ void conv_kernel(int dir, const float* __restrict__ cw, const float* __restrict__ cb) {
    size_t idx = (size_t)blockIdx.x * blockDim.x + threadIdx.x;  // MROWS*CCH
    size_t bt = idx / CCH; int c = (int)(idx % CCH);
    int t = (int)(bt & 2047);
    const float* zx = g_zx[dir];
    float acc = cb[c];
    #pragma unroll
    for (int j = 0; j < 4; j++) {
        int tt = t - 3 + j;
        if (tt >= 0)
            acc += cw[c*4 + j] * zx[(bt + j - 3)*(size_t)DPROJ + DIN + c];
    }
    g_xbc[dir][idx] = siluf(acc);
}

__global__ void dtda_kernel(int dir, const float* __restrict__ dtb, const float* __restrict__ Alog) {
    size_t idx = (size_t)blockIdx.x * blockDim.x + threadIdx.x;  // MROWS*NH
    size_t row = idx >> 4; int hh = (int)(idx & 15);
    float raw = g_zx[dir][row*(size_t)DPROJ + 2*DIN + 2*DS + hh] + dtb[hh];
    float dtv = (raw > 20.f) ? raw : log1pf(expf(raw));
    float dAv = expf(-expf(Alog[hh]) * dtv);
    g_dt[dir][idx] = dtv;
    g_dA[dir][idx] = dAv;
}

// ---------------- sequential SSM scan (sync-free inner loop, f32x2 packed) -------
// 128 blocks = 2 dirs x 4 batch x 16 heads; 512 threads.
// thread -> p = tid>>3 (state row 0..63), ng = tid&7 (owns 16 of 128 state cols).
// y-reduction via shfl within the 8-lane group; no block barrier per timestep.
__global__ void __launch_bounds__(512) scan_kernel(
    const float* __restrict__ Dh_f, const float* __restrict__ Dh_b)
{
    int blk = blockIdx.x;
    int dir = blk >> 6;
    int bh  = blk & 63;
    int b = bh >> 4, hh = bh & 15;
    const float* __restrict__ xbc = g_xbc[dir];
    const float* __restrict__ zx  = g_zx[dir];
    const float* __restrict__ dtb = g_dt[dir];
    const float* __restrict__ dAb = g_dA[dir];
    float* __restrict__ yout = g_y[dir];
    float Dval = (dir ? Dh_b : Dh_f)[hh];

    const int tid = threadIdx.x;
    const int p  = tid >> 3;     // 0..63
    const int ng = tid & 7;      // 0..7 -> n = ng*16 .. +15

    double S2[8];
    #pragma unroll
    for (int i = 0; i < 8; i++) S2[i] = 0.0;   // packed {0.f, 0.f}

    __shared__ float sx[8][64], sz[8][64];
    __shared__ float sB[8][128], sC[8][128];
    __shared__ float sdt[8], sdA[8];
    __shared__ float sy[8][64];

    size_t rowbase = (size_t)b * TLEN;

    for (int c0 = 0; c0 < TLEN; c0 += 8) {
        __syncthreads();   // protect smem reuse from previous chunk's dump
        {
            int t = tid >> 6, pp = tid & 63;
            size_t r = rowbase + c0 + t;
            sx[t][pp] = xbc[r*(size_t)CCH + hh*HD + pp];
            sz[t][pp] = zx [r*(size_t)DPROJ + hh*HD + pp];
        }
        #pragma unroll
        for (int q = 0; q < 2; q++) {
            int idx = tid + q*512;
            int t = idx >> 7, n = idx & 127;
            size_t r = rowbase + c0 + t;
            sB[t][n] = xbc[r*(size_t)CCH + DIN + n];
            sC[t][n] = xbc[r*(size_t)CCH + DIN + DS + n];
        }
        if (tid < 8) {
            size_t r = rowbase + c0 + tid;
            sdt[tid] = dtb[r*NH + hh];
            sdA[tid] = dAb[r*NH + hh];
        }
        __syncthreads();

        #pragma unroll
        for (int t = 0; t < 8; t++) {
            float dtv = sdt[t], dAv = sdA[t];
            float coef = dtv * sx[t][p];
            double dA2, cf2, part2;
            PACK2(dA2, dAv, dAv);
            PACK2(cf2, coef, coef);
            PACK2(part2, 0.f, 0.f);
            const double* B2 = (const double*)&sB[t][ng*16];
            const double* C2 = (const double*)&sC[t][ng*16];
            #pragma unroll
            for (int i = 0; i < 4; i++) {
                double2 bb = *(const double2*)(B2 + 2*i);
                double2 cc = *(const double2*)(C2 + 2*i);
                double tmp;
                MUL2(tmp, bb.x, cf2);
                FMA2(S2[2*i],     dA2, S2[2*i],     tmp);
                FMA2(part2, S2[2*i],     cc.x, part2);
                MUL2(tmp, bb.y, cf2);
                FMA2(S2[2*i + 1], dA2, S2[2*i + 1], tmp);
                FMA2(part2, S2[2*i + 1], cc.y, part2);
            }
            float plo, phi;
            UNPACK2(plo, phi, part2);
            float partial = plo + phi;
            partial += __shfl_xor_sync(0xffffffffu, partial, 1);
            partial += __shfl_xor_sync(0xffffffffu, partial, 2);
            partial += __shfl_xor_sync(0xffffffffu, partial, 4);
            if (ng == 0) sy[t][p] = partial;
        }
        __syncthreads();

        {   // coalesced dump of 8 x 64 outputs
            int t = tid >> 6, pp = tid & 63;
            float y = sy[t][pp];
            float xv = sx[t][pp];
            float zv = sz[t][pp];
            float yv = (y + Dval * xv) * siluf(zv);
            yout[(rowbase + c0 + t)*(size_t)DIN + hh*HD + pp] = yv;
        }
    }
}

__global__ void rms_kernel(float* __restrict__ Y, const float* __restrict__ w) {
    int row = blockIdx.x, tid = threadIdx.x;
    float* yr = Y + (size_t)row * DIN;
    float v[4]; float ss = 0.f;
    #pragma unroll
    for (int i = 0; i < 4; i++) { v[i] = yr[tid + i*256]; ss += v[i]*v[i]; }
    ss = block_reduce(ss);
    float inv = rsqrtf(ss * (1.f/1024.f) + 1e-5f);
    #pragma unroll
    for (int i = 0; i < 4; i++) yr[tid + i*256] = v[i] * inv * w[tid + i*256];
}

__global__ void combine_kernel() {
    size_t idx = (size_t)blockIdx.x * blockDim.x + threadIdx.x;  // MROWS*512
    size_t bt = idx >> 9; int j = (int)(idx & 511);
    int b = (int)(bt >> 11), t = (int)(bt & 2047);
    float hv = g_h[idx];
    float ob = g_od[1][(((size_t)(b << 11) | (2047 - t)) << 9) | j];
    g_u[idx] = (g_od[0][idx] + ob) * siluf(hv);
}

__global__ void lnpost_kernel(const float* __restrict__ vbuf, const float* __restrict__ g,
                              const float* __restrict__ b, float* __restrict__ outdst) {
    int row = blockIdx.x, tid = threadIdx.x;
    float x = vbuf[(size_t)row*DMODEL + tid];
    float mu = block_reduce(x) * (1.f/256.f);
    float d = x - mu;
    float var = block_reduce(d*d) * (1.f/256.f);
    float o = d * rsqrtf(var + 1e-5f) * g[tid] + b[tid] + g_xp[(size_t)row*DMODEL + tid];
    outdst[(size_t)row*DMODEL + tid] = o;
    float ss = block_reduce(o*o);
    float sc = 1.f / fmaxf(sqrtf(ss), 1e-12f);
    g_fn[(size_t)row*DMODEL + tid] = o * sc;
}

// ---------------- launcher ----------------
extern "C" void kernel_launch(void* const* d_in, const int* in_sizes, int n_in,
                              void* d_out, int out_size)
{
    const float* x       = (const float*)d_in[0];
    const float* Wp      = (const float*)d_in[1];
    const float* bp      = (const float*)d_in[2];
    const float* Wpre    = (const float*)d_in[3];
    const float* bpre    = (const float*)d_in[4];
    const float* lnpre_g = (const float*)d_in[5];
    const float* lnpre_b = (const float*)d_in[6];
    const float* Wpost   = (const float*)d_in[7];
    const float* bpost   = (const float*)d_in[8];
    const float* lnpost_g= (const float*)d_in[9];
    const float* lnpost_b= (const float*)d_in[10];
    const float* Win[2]   = {(const float*)d_in[11], (const float*)d_in[19]};
    const float* convw[2] = {(const float*)d_in[12], (const float*)d_in[20]};
    const float* convb[2] = {(const float*)d_in[13], (const float*)d_in[21]};
    const float* dtb[2]   = {(const float*)d_in[14], (const float*)d_in[22]};
    const float* Alog[2]  = {(const float*)d_in[15], (const float*)d_in[23]};
    const float* Dh[2]    = {(const float*)d_in[16], (const float*)d_in[24]};
    const float* normw[2] = {(const float*)d_in[17], (const float*)d_in[25]};
    const float* Wout[2]  = {(const float*)d_in[18], (const float*)d_in[26]};

    static bool attr_done = false;
    if (!attr_done) {
        cudaFuncSetAttribute(tgemm<false>, cudaFuncAttributeMaxDynamicSharedMemorySize, SMEM_NT);
        cudaFuncSetAttribute(tgemm<true>,  cudaFuncAttributeMaxDynamicSharedMemorySize, SMEM_T);
        attr_done = true;
    }

    float *xg, *xp, *pre, *h, *hf, *zxb, *yb, *odb, *u, *v, *fn;
    cudaGetSymbolAddress((void**)&xg,  g_xg);
    cudaGetSymbolAddress((void**)&xp,  g_xp);
    cudaGetSymbolAddress((void**)&pre, g_pre);
    cudaGetSymbolAddress((void**)&h,   g_h);
    cudaGetSymbolAddress((void**)&hf,  g_hf);
    cudaGetSymbolAddress((void**)&zxb, g_zx);
    cudaGetSymbolAddress((void**)&yb,  g_y);
    cudaGetSymbolAddress((void**)&odb, g_od);
    cudaGetSymbolAddress((void**)&u,   g_u);
    cudaGetSymbolAddress((void**)&v,   g_v);
    cudaGetSymbolAddress((void**)&fn,  g_fn);
    float* zx0 = zxb;
    float* zx1 = zxb + (size_t)MROWS*DPROJ;
    float* y0  = yb;
    float* y1  = yb + (size_t)MROWS*DIN;
    float* od0 = odb;
    float* od1 = odb + (size_t)MROWS*DM2;

    float* out  = (float*)d_out;
    float* attn = out + (size_t)MROWS*DMODEL;

    // 1. gather + input projection
    gather_kernel<<<MROWS*768/256, 256>>>(x);
    tgemm<false><<<dim3(DMODEL/128, MROWS/128), 256, SMEM_NT>>>(xg, Wp,   bp,   xp,  MROWS, DMODEL, NSC*DMODEL, 0,0,0);
    // 2. pre-layernorm
    tgemm<false><<<dim3(DM2/128,    MROWS/128), 256, SMEM_NT>>>(xp, Wpre, bpre, pre, MROWS, DM2,    DMODEL,     0,0,0);
    ln512_kernel<<<MROWS, 256>>>(pre, lnpre_g, lnpre_b, h);
    flip_kernel<<<MROWS*DM2/256, 256>>>();
    // 3. mamba in-projections (both directions)
    tgemm<false><<<dim3((DPROJ+127)/128, MROWS/128), 256, SMEM_NT>>>(h,  Win[0], nullptr, zx0, MROWS, DPROJ, DM2, 0,0,0);
    tgemm<false><<<dim3((DPROJ+127)/128, MROWS/128), 256, SMEM_NT>>>(hf, Win[1], nullptr, zx1, MROWS, DPROJ, DM2, 0,0,0);
    // 4. conv + dt/dA
    for (int dir = 0; dir < 2; dir++) {
        conv_kernel<<<MROWS*CCH/256, 256>>>(dir, convw[dir], convb[dir]);
        dtda_kernel<<<MROWS*NH/256, 256>>>(dir, dtb[dir], Alog[dir]);
    }
    // 5. both scans concurrently
    scan_kernel<<<128, 512>>>(Dh[0], Dh[1]);
    // 6. RMS-norm + out-projections
    rms_kernel<<<MROWS, 256>>>(y0, normw[0]);
    rms_kernel<<<MROWS, 256>>>(y1, normw[1]);
    tgemm<false><<<dim3(DM2/128, MROWS/128), 256, SMEM_NT>>>(y0, Wout[0], nullptr, od0, MROWS, DM2, DIN, 0,0,0);
    tgemm<false><<<dim3(DM2/128, MROWS/128), 256, SMEM_NT>>>(y1, Wout[1], nullptr, od1, MROWS, DM2, DIN, 0,0,0);
    // 7. gated combine + post projection + post-LN(+residual) + fn
    combine_kernel<<<MROWS*DM2/256, 256>>>();
    tgemm<false><<<dim3(DMODEL/128, MROWS/128), 256, SMEM_NT>>>(u, Wpost, bpost, v, MROWS, DMODEL, DM2, 0,0,0);
    lnpost_kernel<<<MROWS, 256>>>(v, lnpost_g, lnpost_b, out);
    // 8. attn = fn @ fn^T per batch (B = fn, transposed)
    tgemm<true><<<dim3(TLEN/128, TLEN/128, BATCH), 256, SMEM_T>>>(
        fn, fn, nullptr, attn, TLEN, TLEN, DMODEL,
        (size_t)TLEN*DMODEL, (size_t)TLEN*DMODEL, (size_t)TLEN*TLEN);
}

// round 6
// speedup vs baseline: 1.7421x; 1.7421x over previous
#include <cuda_runtime.h>
#include <cuda_bf16.h>
#include <math.h>
#include <stdint.h>

// ---------------- problem constants ----------------
#define BATCH   4
#define TLEN    2048
#define DMODEL  256
#define NSC     3
#define DM2     512
#define DIN     1024
#define NH      16
#define HD      64
#define DS      128
#define DPROJ   2320     // 2*DIN + 2*DS + NH
#define CCH     1280     // DIN + 2*DS
#define MROWS   (BATCH*TLEN)   // 8192

// ---------------- scratch (device globals; no allocation allowed) ----------------
__device__ float g_xg [(size_t)MROWS*768];
__device__ float g_xp [(size_t)MROWS*DMODEL];
__device__ float g_pre[(size_t)MROWS*DM2];
__device__ float g_h  [(size_t)MROWS*DM2];
__device__ float g_hf [(size_t)MROWS*DM2];
__device__ float g_zx [2][(size_t)MROWS*DPROJ];
__device__ float g_xbc[2][(size_t)MROWS*CCH];
__device__ float g_dt [2][(size_t)MROWS*NH];
__device__ float g_dA [2][(size_t)MROWS*NH];
__device__ float g_y  [2][(size_t)MROWS*DIN];
__device__ float g_od [2][(size_t)MROWS*DM2];
__device__ float g_u  [(size_t)MROWS*DM2];
__device__ float g_v  [(size_t)MROWS*DMODEL];
__device__ float g_fn [(size_t)MROWS*DMODEL];

// ---------------- helpers ----------------
__device__ __forceinline__ float siluf(float x) { return x / (1.f + __expf(-x)); }

__device__ __forceinline__ void mma_bf16(float c[4], const uint32_t a[4], const uint32_t b[2]) {
    asm volatile("mma.sync.aligned.m16n8k16.row.col.f32.bf16.bf16.f32 "
        "{%0,%1,%2,%3}, {%4,%5,%6,%7}, {%8,%9}, {%0,%1,%2,%3};"
        : "+f"(c[0]), "+f"(c[1]), "+f"(c[2]), "+f"(c[3])
        : "r"(a[0]), "r"(a[1]), "r"(a[2]), "r"(a[3]), "r"(b[0]), "r"(b[1]));
}

// split two floats into packed bf16 hi-word and lo-word (low 16 bits = first arg)
__device__ __forceinline__ void pksplit(float a, float b, uint32_t& h, uint32_t& l) {
    __nv_bfloat16 ha = __float2bfloat16(a), hb = __float2bfloat16(b);
    float ra = a - __bfloat162float(ha);
    float rb = b - __bfloat162float(hb);
    __nv_bfloat162 hh; hh.x = ha; hh.y = hb;
    __nv_bfloat162 ll; ll.x = __float2bfloat16(ra); ll.y = __float2bfloat16(rb);
    h = *(uint32_t*)&hh; l = *(uint32_t*)&ll;
}

// packed f32x2 ops (sm_103a FFMA2 path; only reachable via PTX)
#define FMA2(d, a, b, c) asm("fma.rn.f32x2 %0, %1, %2, %3;" : "=d"(d) : "d"(a), "d"(b), "d"(c))
#define MUL2(d, a, b)    asm("mul.rn.f32x2 %0, %1, %2;"     : "=d"(d) : "d"(a), "d"(b))
#define PACK2(d, lo, hi) asm("mov.b64 %0, {%1, %2};"        : "=d"(d) : "f"(lo), "f"(hi))
#define UNPACK2(lo, hi, s) asm("mov.b64 {%0, %1}, %2;"      : "=f"(lo), "=f"(hi) : "d"(s))

__device__ __forceinline__ float block_reduce(float v) {
    __shared__ float sb[33];
    int lane = threadIdx.x & 31, w = threadIdx.x >> 5;
    #pragma unroll
    for (int o = 16; o; o >>= 1) v += __shfl_xor_sync(0xffffffffu, v, o);
    __syncthreads();
    if (lane == 0) sb[w] = v;
    __syncthreads();
    int nw = blockDim.x >> 5;
    float r = (threadIdx.x < nw) ? sb[threadIdx.x] : 0.f;
    if (w == 0) {
        #pragma unroll
        for (int o = 8; o; o >>= 1) r += __shfl_xor_sync(0xffffffffu, r, o);
        if (lane == 0) sb[32] = r;
    }
    __syncthreads();
    return sb[32];
}

// ---------------- split-bf16 tensor-core GEMM (~17 mantissa bits) ----------------
#define ASTRW   1536    // A planes: [128 rows][pitch 12]
#define BSTRW_T 1536    // TRANSB B: same layout as A
#define BSTRW_N 1088    // !TRANSB B: [8 kp][pitch 136]  (conflict-free frag loads)

template<bool TRANSB>
__global__ void __launch_bounds__(256) tgemm(
    const float* __restrict__ A, const float* __restrict__ B,
    const float* __restrict__ bias, float* __restrict__ C,
    int M, int N, int K, size_t sA, size_t sB, size_t sC)
{
    A += (size_t)blockIdx.z * sA;
    B += (size_t)blockIdx.z * sB;
    C += (size_t)blockIdx.z * sC;

    extern __shared__ uint32_t sm[];
    constexpr int BSTRW = TRANSB ? BSTRW_T : BSTRW_N;
    uint32_t* As = sm;                 // 4 planes: (buf*2 + hl)*ASTRW
    uint32_t* Bs = sm + 4*ASTRW;       // 4 planes: (buf*2 + hl)*BSTRW

    const int tid = threadIdx.x;
    const int m0 = blockIdx.y * 128, n0 = blockIdx.x * 128;
    const int lane = tid & 31, w = tid >> 5;
    const int wm = (w & 1) * 64, wn = (w >> 1) * 32;
    const int g = lane >> 2, tq = lane & 3;

    float acc[4][4][4];
    #pragma unroll
    for (int i = 0; i < 4; i++)
        #pragma unroll
        for (int j = 0; j < 4; j++)
            #pragma unroll
            for (int q = 0; q < 4; q++) acc[i][j][q] = 0.f;

    const int aRow = tid >> 1;
    const int aK   = (tid & 1) * 8;
    const int bKp = tid >> 5;
    const int bN  = (tid & 31) * 4;

    float4 ra[2], rb[2];

    auto loadG = [&](int kc) {
        const float* Ar = A + (size_t)(m0 + aRow)*K + kc + aK;
        ra[0] = *(const float4*)(Ar);
        ra[1] = *(const float4*)(Ar + 4);
        if (TRANSB) {
            const float* Br = B + (size_t)(n0 + aRow)*K + kc + aK;
            rb[0] = *(const float4*)(Br);
            rb[1] = *(const float4*)(Br + 4);
        } else {
            if (n0 + bN < N) {
                rb[0] = *(const float4*)(B + (size_t)(kc + 2*bKp    )*N + n0 + bN);
                rb[1] = *(const float4*)(B + (size_t)(kc + 2*bKp + 1)*N + n0 + bN);
            } else {
                rb[0] = make_float4(0.f,0.f,0.f,0.f);
                rb[1] = make_float4(0.f,0.f,0.f,0.f);
            }
        }
    };
    auto storeS = [&](int buf) {
        uint32_t* ah = As + (buf*2    )*ASTRW;
        uint32_t* al = As + (buf*2 + 1)*ASTRW;
        uint32_t* bh = Bs + (buf*2    )*BSTRW;
        uint32_t* bl = Bs + (buf*2 + 1)*BSTRW;
        uint4 h4, l4;
        pksplit(ra[0].x, ra[0].y, h4.x, l4.x);
        pksplit(ra[0].z, ra[0].w, h4.y, l4.y);
        pksplit(ra[1].x, ra[1].y, h4.z, l4.z);
        pksplit(ra[1].z, ra[1].w, h4.w, l4.w);
        *(uint4*)(ah + aRow*12 + aK/2) = h4;
        *(uint4*)(al + aRow*12 + aK/2) = l4;
        if (TRANSB) {
            pksplit(rb[0].x, rb[0].y, h4.x, l4.x);
            pksplit(rb[0].z, rb[0].w, h4.y, l4.y);
            pksplit(rb[1].x, rb[1].y, h4.z, l4.z);
            pksplit(rb[1].z, rb[1].w, h4.w, l4.w);
            *(uint4*)(bh + aRow*12 + aK/2) = h4;
            *(uint4*)(bl + aRow*12 + aK/2) = l4;
        } else {
            pksplit(rb[0].x, rb[1].x, h4.x, l4.x);
            pksplit(rb[0].y, rb[1].y, h4.y, l4.y);
            pksplit(rb[0].z, rb[1].z, h4.z, l4.z);
            pksplit(rb[0].w, rb[1].w, h4.w, l4.w);
            *(uint4*)(bh + bKp*136 + bN) = h4;
            *(uint4*)(bl + bKp*136 + bN) = l4;
        }
    };

    loadG(0); storeS(0); __syncthreads();
    const int nCh = K >> 4;
    for (int c = 0; c < nCh; c++) {
        int buf = c & 1;
        if (c + 1 < nCh) loadG((c + 1) << 4);
        const uint32_t* ah = As + (buf*2    )*ASTRW;
        const uint32_t* al = As + (buf*2 + 1)*ASTRW;
        const uint32_t* bh = Bs + (buf*2    )*BSTRW;
        const uint32_t* bl = Bs + (buf*2 + 1)*BSTRW;

        uint32_t afh[4][4], afl[4][4], bfh[4][2], bfl[4][2];
        #pragma unroll
        for (int mi = 0; mi < 4; mi++) {
            int mr = wm + mi*16 + g;
            int i0 =  mr     *12 + tq;
            int i1 = (mr + 8)*12 + tq;
            afh[mi][0] = ah[i0];     afh[mi][1] = ah[i1];
            afh[mi][2] = ah[i0 + 4]; afh[mi][3] = ah[i1 + 4];
            afl[mi][0] = al[i0];     afl[mi][1] = al[i1];
            afl[mi][2] = al[i0 + 4]; afl[mi][3] = al[i1 + 4];
        }
        #pragma unroll
        for (int ni = 0; ni < 4; ni++) {
            int nc = wn + ni*8 + g;
            if (TRANSB) {
                int i0 = nc*12 + tq;
                bfh[ni][0] = bh[i0]; bfh[ni][1] = bh[i0 + 4];
                bfl[ni][0] = bl[i0]; bfl[ni][1] = bl[i0 + 4];
            } else {
                int i0 =  tq     *136 + nc;
                int i1 = (tq + 4)*136 + nc;
                bfh[ni][0] = bh[i0]; bfh[ni][1] = bh[i1];
                bfl[ni][0] = bl[i0]; bfl[ni][1] = bl[i1];
            }
        }
        #pragma unroll
        for (int mi = 0; mi < 4; mi++)
            #pragma unroll
            for (int ni = 0; ni < 4; ni++) {
                mma_bf16(acc[mi][ni], afh[mi], bfh[ni]);
                mma_bf16(acc[mi][ni], afh[mi], bfl[ni]);
                mma_bf16(acc[mi][ni], afl[mi], bfh[ni]);
            }
        if (c + 1 < nCh) { __syncthreads(); storeS(buf ^ 1); __syncthreads(); }
    }

    #pragma unroll
    for (int mi = 0; mi < 4; mi++) {
        int row = m0 + wm + mi*16 + g;
        #pragma unroll
        for (int ni = 0; ni < 4; ni++) {
            int col = n0 + wn + ni*8 + tq*2;
            if (col < N) {
                float b0v = bias ? bias[col]     : 0.f;
                float b1v = bias ? bias[col + 1] : 0.f;
                float2 v0; v0.x = acc[mi][ni][0] + b0v; v0.y = acc[mi][ni][1] + b1v;
                float2 v1; v1.x = acc[mi][ni][2] + b0v; v1.y = acc[mi][ni][3] + b1v;
                *(float2*)(C + (size_t)row*N + col)       = v0;
                *(float2*)(C + (size_t)(row + 8)*N + col) = v1;
            }
        }
    }
}

#define SMEM_NT ((4*ASTRW + 4*BSTRW_N)*4)   // 41984 bytes
#define SMEM_T  ((4*ASTRW + 4*BSTRW_T)*4)   // 49152 bytes

// ---------------- elementwise kernels ----------------
__global__ void gather_kernel(const float* __restrict__ x) {
    size_t idx = (size_t)blockIdx.x * blockDim.x + threadIdx.x;  // MROWS*768 exact
    size_t bt = idx / 768; int r = (int)(idx % 768);
    int s = r >> 8, d = r & 255;
    int b = (int)(bt >> 11), t = (int)(bt & 2047);
    g_xg[idx] = x[(((size_t)(b*NSC + s)*TLEN + t) << 8) + d];
}

__global__ void flip_kernel() {
    size_t idx = (size_t)blockIdx.x * blockDim.x + threadIdx.x;  // MROWS*512
    size_t bt = idx >> 9; int j = (int)(idx & 511);
    int b = (int)(bt >> 11), t = (int)(bt & 2047);
    g_hf[idx] = g_h[(((size_t)(b << 11) | (2047 - t)) << 9) | j];
}

__global__ void ln512_kernel(const float* __restrict__ in, const float* __restrict__ g,
                             const float* __restrict__ b, float* __restrict__ out) {
    int row = blockIdx.x, tid = threadIdx.x;
    const float* xr = in + (size_t)row * DM2;
    float v0 = xr[tid], v1 = xr[tid + 256];
    float mu = block_reduce(v0 + v1) * (1.f / 512.f);
    float d0 = v0 - mu, d1 = v1 - mu;
    float var = block_reduce(d0*d0 + d1*d1) * (1.f / 512.f);
    float inv = rsqrtf(var + 1e-5f);
    out[(size_t)row*DM2 + tid]       = d0 * inv * g[tid]       + b[tid];
    out[(size_t)row*DM2 + tid + 256] = d1 * inv * g[tid + 256] + b[tid + 256];
}

__global__ void conv_kernel(int dir, const float* __restrict__ cw, const float* __restrict__ cb) {
    size_t idx = (size_t)blockIdx.x * blockDim.x + threadIdx.x;  // MROWS*CCH
    size_t bt = idx / CCH; int c = (int)(idx % CCH);
    int t = (int)(bt & 2047);
    const float* zx = g_zx[dir];
    float acc = cb[c];
    #pragma unroll
    for (int j = 0; j < 4; j++) {
        int tt = t - 3 + j;
        if (tt >= 0)
            acc += cw[c*4 + j] * zx[(bt + j - 3)*(size_t)DPROJ + DIN + c];
    }
    g_xbc[dir][idx] = siluf(acc);
}

__global__ void dtda_kernel(int dir, const float* __restrict__ dtb, const float* __restrict__ Alog) {
    size_t idx = (size_t)blockIdx.x * blockDim.x + threadIdx.x;  // MROWS*NH
    size_t row = idx >> 4; int hh = (int)(idx & 15);
    float raw = g_zx[dir][row*(size_t)DPROJ + 2*DIN + 2*DS + hh] + dtb[hh];
    float dtv = (raw > 20.f) ? raw : log1pf(expf(raw));
    float dAv = expf(-expf(Alog[hh]) * dtv);
    g_dt[dir][idx] = dtv;
    g_dA[dir][idx] = dAv;
}

// ---------------- sequential SSM scan (sync-free inner loop, f32x2 packed) -------
// 128 blocks = 2 dirs x 4 batch x 16 heads; 512 threads.
// thread -> p = tid>>3 (state row 0..63), ng = tid&7 (owns 16 of 128 state cols).
// B/C rows stored with per-ng-group pitch 20 floats: group bases mod 32 =
// {0,20,8,28,16,4,24,12}; each LDS.128 phase (8 lanes, distinct ng) covers all
// 32 banks exactly once -> conflict-free. 80-byte group stride keeps 16B align.
#define GP 20
__global__ void __launch_bounds__(512) scan_kernel(
    const float* __restrict__ Dh_f, const float* __restrict__ Dh_b)
{
    int blk = blockIdx.x;
    int dir = blk >> 6;
    int bh  = blk & 63;
    int b = bh >> 4, hh = bh & 15;
    const float* __restrict__ xbc = g_xbc[dir];
    const float* __restrict__ zx  = g_zx[dir];
    const float* __restrict__ dtb = g_dt[dir];
    const float* __restrict__ dAb = g_dA[dir];
    float* __restrict__ yout = g_y[dir];
    float Dval = (dir ? Dh_b : Dh_f)[hh];

    const int tid = threadIdx.x;
    const int p  = tid >> 3;     // 0..63
    const int ng = tid & 7;      // 0..7 -> n = ng*16 .. +15

    double S2[8];
    #pragma unroll
    for (int i = 0; i < 8; i++) S2[i] = 0.0;   // packed {0.f, 0.f}

    __shared__ float sx[8][64], sz[8][64];
    __shared__ float sB[8][8*GP], sC[8][8*GP];
    __shared__ float sdt[8], sdA[8];
    __shared__ float sy[8][64];

    size_t rowbase = (size_t)b * TLEN;

    for (int c0 = 0; c0 < TLEN; c0 += 8) {
        __syncthreads();   // protect smem reuse from previous chunk's dump
        {
            int t = tid >> 6, pp = tid & 63;
            size_t r = rowbase + c0 + t;
            sx[t][pp] = xbc[r*(size_t)CCH + hh*HD + pp];
            sz[t][pp] = zx [r*(size_t)DPROJ + hh*HD + pp];
        }
        #pragma unroll
        for (int q = 0; q < 2; q++) {
            int idx = tid + q*512;
            int t = idx >> 7, n = idx & 127;
            int off = (n >> 4)*GP + (n & 15);
            size_t r = rowbase + c0 + t;
            sB[t][off] = xbc[r*(size_t)CCH + DIN + n];
            sC[t][off] = xbc[r*(size_t)CCH + DIN + DS + n];
        }
        if (tid < 8) {
            size_t r = rowbase + c0 + tid;
            sdt[tid] = dtb[r*NH + hh];
            sdA[tid] = dAb[r*NH + hh];
        }
        __syncthreads();

        #pragma unroll
        for (int t = 0; t < 8; t++) {
            float dtv = sdt[t], dAv = sdA[t];
            float coef = dtv * sx[t][p];
            double dA2, cf2, part2;
            PACK2(dA2, dAv, dAv);
            PACK2(cf2, coef, coef);
            PACK2(part2, 0.f, 0.f);
            const double* B2 = (const double*)&sB[t][ng*GP];
            const double* C2 = (const double*)&sC[t][ng*GP];
            #pragma unroll
            for (int i = 0; i < 4; i++) {
                double2 bb = *(const double2*)(B2 + 2*i);
                double2 cc = *(const double2*)(C2 + 2*i);
                double tmp;
                MUL2(tmp, bb.x, cf2);
                FMA2(S2[2*i],     dA2, S2[2*i],     tmp);
                FMA2(part2, S2[2*i],     cc.x, part2);
                MUL2(tmp, bb.y, cf2);
                FMA2(S2[2*i + 1], dA2, S2[2*i + 1], tmp);
                FMA2(part2, S2[2*i + 1], cc.y, part2);
            }
            float plo, phi;
            UNPACK2(plo, phi, part2);
            float partial = plo + phi;
            partial += __shfl_xor_sync(0xffffffffu, partial, 1);
            partial += __shfl_xor_sync(0xffffffffu, partial, 2);
            partial += __shfl_xor_sync(0xffffffffu, partial, 4);
            if (ng == 0) sy[t][p] = partial;
        }
        __syncthreads();

        {   // coalesced dump of 8 x 64 outputs
            int t = tid >> 6, pp = tid & 63;
            float y = sy[t][pp];
            float xv = sx[t][pp];
            float zv = sz[t][pp];
            float yv = (y + Dval * xv) * siluf(zv);
            yout[(rowbase + c0 + t)*(size_t)DIN + hh*HD + pp] = yv;
        }
    }
}

__global__ void rms_kernel(float* __restrict__ Y, const float* __restrict__ w) {
    int row = blockIdx.x, tid = threadIdx.x;
    float* yr = Y + (size_t)row * DIN;
    float v[4]; float ss = 0.f;
    #pragma unroll
    for (int i = 0; i < 4; i++) { v[i] = yr[tid + i*256]; ss += v[i]*v[i]; }
    ss = block_reduce(ss);
    float inv = rsqrtf(ss * (1.f/1024.f) + 1e-5f);
    #pragma unroll
    for (int i = 0; i < 4; i++) yr[tid + i*256] = v[i] * inv * w[tid + i*256];
}

__global__ void combine_kernel() {
    size_t idx = (size_t)blockIdx.x * blockDim.x + threadIdx.x;  // MROWS*512
    size_t bt = idx >> 9; int j = (int)(idx & 511);
    int b = (int)(bt >> 11), t = (int)(bt & 2047);
    float hv = g_h[idx];
    float ob = g_od[1][(((size_t)(b << 11) | (2047 - t)) << 9) | j];
    g_u[idx] = (g_od[0][idx] + ob) * siluf(hv);
}

__global__ void lnpost_kernel(const float* __restrict__ vbuf, const float* __restrict__ g,
                              const float* __restrict__ b, float* __restrict__ outdst) {
    int row = blockIdx.x, tid = threadIdx.x;
    float x = vbuf[(size_t)row*DMODEL + tid];
    float mu = block_reduce(x) * (1.f/256.f);
    float d = x - mu;
    float var = block_reduce(d*d) * (1.f/256.f);
    float o = d * rsqrtf(var + 1e-5f) * g[tid] + b[tid] + g_xp[(size_t)row*DMODEL + tid];
    outdst[(size_t)row*DMODEL + tid] = o;
    float ss = block_reduce(o*o);
    float sc = 1.f / fmaxf(sqrtf(ss), 1e-12f);
    g_fn[(size_t)row*DMODEL + tid] = o * sc;
}

// ---------------- launcher ----------------
extern "C" void kernel_launch(void* const* d_in, const int* in_sizes, int n_in,
                              void* d_out, int out_size)
{
    const float* x       = (const float*)d_in[0];
    const float* Wp      = (const float*)d_in[1];
    const float* bp      = (const float*)d_in[2];
    const float* Wpre    = (const float*)d_in[3];
    const float* bpre    = (const float*)d_in[4];
    const float* lnpre_g = (const float*)d_in[5];
    const float* lnpre_b = (const float*)d_in[6];
    const float* Wpost   = (const float*)d_in[7];
    const float* bpost   = (const float*)d_in[8];
    const float* lnpost_g= (const float*)d_in[9];
    const float* lnpost_b= (const float*)d_in[10];
    const float* Win[2]   = {(const float*)d_in[11], (const float*)d_in[19]};
    const float* convw[2] = {(const float*)d_in[12], (const float*)d_in[20]};
    const float* convb[2] = {(const float*)d_in[13], (const float*)d_in[21]};
    const float* dtb[2]   = {(const float*)d_in[14], (const float*)d_in[22]};
    const float* Alog[2]  = {(const float*)d_in[15], (const float*)d_in[23]};
    const float* Dh[2]    = {(const float*)d_in[16], (const float*)d_in[24]};
    const float* normw[2] = {(const float*)d_in[17], (const float*)d_in[25]};
    const float* Wout[2]  = {(const float*)d_in[18], (const float*)d_in[26]};

    static bool attr_done = false;
    if (!attr_done) {
        cudaFuncSetAttribute(tgemm<false>, cudaFuncAttributeMaxDynamicSharedMemorySize, SMEM_NT);
        cudaFuncSetAttribute(tgemm<true>,  cudaFuncAttributeMaxDynamicSharedMemorySize, SMEM_T);
        attr_done = true;
    }

    float *xg, *xp, *pre, *h, *hf, *zxb, *yb, *odb, *u, *v, *fn;
    cudaGetSymbolAddress((void**)&xg,  g_xg);
    cudaGetSymbolAddress((void**)&xp,  g_xp);
    cudaGetSymbolAddress((void**)&pre, g_pre);
    cudaGetSymbolAddress((void**)&h,   g_h);
    cudaGetSymbolAddress((void**)&hf,  g_hf);
    cudaGetSymbolAddress((void**)&zxb, g_zx);
    cudaGetSymbolAddress((void**)&yb,  g_y);
    cudaGetSymbolAddress((void**)&odb, g_od);
    cudaGetSymbolAddress((void**)&u,   g_u);
    cudaGetSymbolAddress((void**)&v,   g_v);
    cudaGetSymbolAddress((void**)&fn,  g_fn);
    float* zx0 = zxb;
    float* zx1 = zxb + (size_t)MROWS*DPROJ;
    float* y0  = yb;
    float* y1  = yb + (size_t)MROWS*DIN;
    float* od0 = odb;
    float* od1 = odb + (size_t)MROWS*DM2;

    float* out  = (float*)d_out;
    float* attn = out + (size_t)MROWS*DMODEL;

    // 1. gather + input projection
    gather_kernel<<<MROWS*768/256, 256>>>(x);
    tgemm<false><<<dim3(DMODEL/128, MROWS/128), 256, SMEM_NT>>>(xg, Wp,   bp,   xp,  MROWS, DMODEL, NSC*DMODEL, 0,0,0);
    // 2. pre-layernorm
    tgemm<false><<<dim3(DM2/128,    MROWS/128), 256, SMEM_NT>>>(xp, Wpre, bpre, pre, MROWS, DM2,    DMODEL,     0,0,0);
    ln512_kernel<<<MROWS, 256>>>(pre, lnpre_g, lnpre_b, h);
    flip_kernel<<<MROWS*DM2/256, 256>>>();
    // 3. mamba in-projections (both directions)
    tgemm<false><<<dim3((DPROJ+127)/128, MROWS/128), 256, SMEM_NT>>>(h,  Win[0], nullptr, zx0, MROWS, DPROJ, DM2, 0,0,0);
    tgemm<false><<<dim3((DPROJ+127)/128, MROWS/128), 256, SMEM_NT>>>(hf, Win[1], nullptr, zx1, MROWS, DPROJ, DM2, 0,0,0);
    // 4. conv + dt/dA
    for (int dir = 0; dir < 2; dir++) {
        conv_kernel<<<MROWS*CCH/256, 256>>>(dir, convw[dir], convb[dir]);
        dtda_kernel<<<MROWS*NH/256, 256>>>(dir, dtb[dir], Alog[dir]);
    }
    // 5. both scans concurrently
    scan_kernel<<<128, 512>>>(Dh[0], Dh[1]);
    // 6. RMS-norm + out-projections
    rms_kernel<<<MROWS, 256>>>(y0, normw[0]);
    rms_kernel<<<MROWS, 256>>>(y1, normw[1]);
    tgemm<false><<<dim3(DM2/128, MROWS/128), 256, SMEM_NT>>>(y0, Wout[0], nullptr, od0, MROWS, DM2, DIN, 0,0,0);
    tgemm<false><<<dim3(DM2/128, MROWS/128), 256, SMEM_NT>>>(y1, Wout[1], nullptr, od1, MROWS, DM2, DIN, 0,0,0);
    // 7. gated combine + post projection + post-LN(+residual) + fn
    combine_kernel<<<MROWS*DM2/256, 256>>>();
    tgemm<false><<<dim3(DMODEL/128, MROWS/128), 256, SMEM_NT>>>(u, Wpost, bpost, v, MROWS, DMODEL, DM2, 0,0,0);
    lnpost_kernel<<<MROWS, 256>>>(v, lnpost_g, lnpost_b, out);
    // 8. attn = fn @ fn^T per batch (B = fn, transposed)
    tgemm<true><<<dim3(TLEN/128, TLEN/128, BATCH), 256, SMEM_T>>>(
        fn, fn, nullptr, attn, TLEN, TLEN, DMODEL,
        (size_t)TLEN*DMODEL, (size_t)TLEN*DMODEL, (size_t)TLEN*TLEN);
}

// round 7
// speedup vs baseline: 1.9055x; 1.0938x over previous
#include <cuda_runtime.h>
#include <cuda_bf16.h>
#include <math.h>
#include <stdint.h>

// ---------------- problem constants ----------------
#define BATCH   4
#define TLEN    2048
#define DMODEL  256
#define NSC     3
#define DM2     512
#define DIN     1024
#define NH      16
#define HD      64
#define DS      128
#define DPROJ   2320     // 2*DIN + 2*DS + NH
#define CCH     1280     // DIN + 2*DS
#define MROWS   (BATCH*TLEN)   // 8192

// ---------------- scratch (device globals; no allocation allowed) ----------------
__device__ float g_xg [(size_t)MROWS*768];
__device__ float g_xp [(size_t)MROWS*DMODEL];
__device__ float g_pre[(size_t)MROWS*DM2];
__device__ float g_h  [(size_t)MROWS*DM2];
__device__ float g_hf [(size_t)MROWS*DM2];
__device__ float g_zx [2][(size_t)MROWS*DPROJ];
__device__ float g_xbc[2][(size_t)MROWS*CCH];
__device__ float g_dt [2][(size_t)MROWS*NH];
__device__ float g_dA [2][(size_t)MROWS*NH];
__device__ float g_y  [2][(size_t)MROWS*DIN];
__device__ float g_od [2][(size_t)MROWS*DM2];
__device__ float g_u  [(size_t)MROWS*DM2];
__device__ float g_v  [(size_t)MROWS*DMODEL];
__device__ float g_fn [(size_t)MROWS*DMODEL];
__device__ float g_wt [3883008];     // transposed weights, offsets below

// offsets into g_wt (floats)
#define OFF_WPT    0
#define OFF_WPRET  196608
#define OFF_WINT0  327680
#define OFF_WINT1  1515520
#define OFF_WOUTT0 2703360
#define OFF_WOUTT1 3227648
#define OFF_WPOSTT 3751936

// ---------------- helpers ----------------
__device__ __forceinline__ float siluf(float x) { return x / (1.f + __expf(-x)); }

__device__ __forceinline__ void mma_bf16(float c[4], const uint32_t a[4], const uint32_t b[2]) {
    asm volatile("mma.sync.aligned.m16n8k16.row.col.f32.bf16.bf16.f32 "
        "{%0,%1,%2,%3}, {%4,%5,%6,%7}, {%8,%9}, {%0,%1,%2,%3};"
        : "+f"(c[0]), "+f"(c[1]), "+f"(c[2]), "+f"(c[3])
        : "r"(a[0]), "r"(a[1]), "r"(a[2]), "r"(a[3]), "r"(b[0]), "r"(b[1]));
}

__device__ __forceinline__ void ldsm4(uint32_t r[4], uint32_t addr) {
    asm volatile("ldmatrix.sync.aligned.m8n8.x4.shared.b16 {%0,%1,%2,%3}, [%4];"
        : "=r"(r[0]), "=r"(r[1]), "=r"(r[2]), "=r"(r[3]) : "r"(addr));
}

// split two floats into packed bf16 hi-word and lo-word (low 16 bits = first arg)
__device__ __forceinline__ void pksplit(float a, float b, uint32_t& h, uint32_t& l) {
    __nv_bfloat16 ha = __float2bfloat16(a), hb = __float2bfloat16(b);
    float ra = a - __bfloat162float(ha);
    float rb = b - __bfloat162float(hb);
    __nv_bfloat162 hh; hh.x = ha; hh.y = hb;
    __nv_bfloat162 ll; ll.x = __float2bfloat16(ra); ll.y = __float2bfloat16(rb);
    h = *(uint32_t*)&hh; l = *(uint32_t*)&ll;
}

// packed f32x2 ops (sm_103a FFMA2 path; only reachable via PTX)
#define FMA2(d, a, b, c) asm("fma.rn.f32x2 %0, %1, %2, %3;" : "=d"(d) : "d"(a), "d"(b), "d"(c))
#define MUL2(d, a, b)    asm("mul.rn.f32x2 %0, %1, %2;"     : "=d"(d) : "d"(a), "d"(b))
#define PACK2(d, lo, hi) asm("mov.b64 %0, {%1, %2};"        : "=d"(d) : "f"(lo), "f"(hi))
#define UNPACK2(lo, hi, s) asm("mov.b64 {%0, %1}, %2;"      : "=f"(lo), "=f"(hi) : "d"(s))

__device__ __forceinline__ float block_reduce(float v) {
    __shared__ float sb[33];
    int lane = threadIdx.x & 31, w = threadIdx.x >> 5;
    #pragma unroll
    for (int o = 16; o; o >>= 1) v += __shfl_xor_sync(0xffffffffu, v, o);
    __syncthreads();
    if (lane == 0) sb[w] = v;
    __syncthreads();
    int nw = blockDim.x >> 5;
    float r = (threadIdx.x < nw) ? sb[threadIdx.x] : 0.f;
    if (w == 0) {
        #pragma unroll
        for (int o = 8; o; o >>= 1) r += __shfl_xor_sync(0xffffffffu, r, o);
        if (lane == 0) sb[32] = r;
    }
    __syncthreads();
    return sb[32];
}

// ---------------- weight transpose: WT[n][k] = W[k][n] ----------------
__global__ void transpose_kernel(const float* __restrict__ W, float* __restrict__ WT,
                                 int K, int N) {
    __shared__ float tile[32][33];
    int k0 = blockIdx.y * 32, n0 = blockIdx.x * 32;
    int tx = threadIdx.x, ty = threadIdx.y;   // 32 x 8
    for (int i = ty; i < 32; i += 8)
        if (k0 + i < K && n0 + tx < N) tile[i][tx] = W[(size_t)(k0 + i)*N + n0 + tx];
    __syncthreads();
    for (int i = ty; i < 32; i += 8)
        if (n0 + i < N && k0 + tx < K) WT[(size_t)(n0 + i)*K + k0 + tx] = tile[tx][i];
}

// ---------------- split-bf16 tensor-core GEMM, ldmatrix fragments --------------
// C[M,N] = A[M,K] @ B^T (+bias).  A [M,K] rm, B [N,K] rm.
// x = hi + lo (bf16 each); hi*hi + hi*lo + lo*hi  (~17 mantissa bits).
// Block tile 128x128, BK=16, 256 threads (8 warps = 2Mx4N of 64x32 warp tiles).
// M % 128 == 0, K % 16 == 0; N row-guarded.
// Smem: A and B both [128 rows][pitch 12 words]; words = bf16x2 along K.
#define ASTRW 1536

__global__ void __launch_bounds__(256) tgemmT(
    const float* __restrict__ A, const float* __restrict__ B,
    const float* __restrict__ bias, float* __restrict__ C,
    int M, int N, int K, size_t sA, size_t sB, size_t sC)
{
    A += (size_t)blockIdx.z * sA;
    B += (size_t)blockIdx.z * sB;
    C += (size_t)blockIdx.z * sC;

    extern __shared__ uint32_t sm[];
    uint32_t* As = sm;                 // planes (buf*2 + hl)*ASTRW
    uint32_t* Bs = sm + 4*ASTRW;
    const uint32_t smemBase = (uint32_t)__cvta_generic_to_shared(sm);

    const int tid = threadIdx.x;
    const int m0 = blockIdx.y * 128, n0 = blockIdx.x * 128;
    const int lane = tid & 31, w = tid >> 5;
    const int wm = (w & 1) * 64, wn = (w >> 1) * 32;
    const int g = lane >> 2, tq = lane & 3;

    float acc[4][4][4];
    #pragma unroll
    for (int i = 0; i < 4; i++)
        #pragma unroll
        for (int j = 0; j < 4; j++)
            #pragma unroll
            for (int q = 0; q < 4; q++) acc[i][j][q] = 0.f;

    const int aRow = tid >> 1;
    const int aK   = (tid & 1) * 8;

    // ldmatrix per-lane address offsets (bytes)
    const int aoff = ((wm + (lane & 15))*12 + ((lane >> 4) << 2)) * 4;
    const int boff = ((wn + (lane & 7) + ((lane & 16) >> 1))*12 + ((lane & 8) >> 1)) * 4;

    float4 ra[2], rb[2];

    auto loadG = [&](int kc) {
        const float* Ar = A + (size_t)(m0 + aRow)*K + kc + aK;
        ra[0] = *(const float4*)(Ar);
        ra[1] = *(const float4*)(Ar + 4);
        if (n0 + aRow < N) {
            const float* Br = B + (size_t)(n0 + aRow)*K + kc + aK;
            rb[0] = *(const float4*)(Br);
            rb[1] = *(const float4*)(Br + 4);
        } else {
            rb[0] = make_float4(0.f,0.f,0.f,0.f);
            rb[1] = make_float4(0.f,0.f,0.f,0.f);
        }
    };
    auto storeS = [&](int buf) {
        uint32_t* ah = As + (buf*2    )*ASTRW;
        uint32_t* al = As + (buf*2 + 1)*ASTRW;
        uint32_t* bh = Bs + (buf*2    )*ASTRW;
        uint32_t* bl = Bs + (buf*2 + 1)*ASTRW;
        uint4 h4, l4;
        pksplit(ra[0].x, ra[0].y, h4.x, l4.x);
        pksplit(ra[0].z, ra[0].w, h4.y, l4.y);
        pksplit(ra[1].x, ra[1].y, h4.z, l4.z);
        pksplit(ra[1].z, ra[1].w, h4.w, l4.w);
        *(uint4*)(ah + aRow*12 + aK/2) = h4;
        *(uint4*)(al + aRow*12 + aK/2) = l4;
        pksplit(rb[0].x, rb[0].y, h4.x, l4.x);
        pksplit(rb[0].z, rb[0].w, h4.y, l4.y);
        pksplit(rb[1].x, rb[1].y, h4.z, l4.z);
        pksplit(rb[1].z, rb[1].w, h4.w, l4.w);
        *(uint4*)(bh + aRow*12 + aK/2) = h4;
        *(uint4*)(bl + aRow*12 + aK/2) = l4;
    };

    loadG(0); storeS(0); __syncthreads();
    const int nCh = K >> 4;
    for (int c = 0; c < nCh; c++) {
        int buf = c & 1;
        if (c + 1 < nCh) loadG((c + 1) << 4);

        uint32_t aH = smemBase + (buf*2*ASTRW)*4 + aoff;
        uint32_t aL = aH + ASTRW*4;
        uint32_t bH = smemBase + (4*ASTRW + buf*2*ASTRW)*4 + boff;
        uint32_t bL = bH + ASTRW*4;

        uint32_t afh[4][4], afl[4][4], bh4[2][4], bl4[2][4];
        #pragma unroll
        for (int mi = 0; mi < 4; mi++) {
            ldsm4(afh[mi], aH + mi*768);
            ldsm4(afl[mi], aL + mi*768);
        }
        #pragma unroll
        for (int p2 = 0; p2 < 2; p2++) {
            ldsm4(bh4[p2], bH + p2*768);
            ldsm4(bl4[p2], bL + p2*768);
        }
        #pragma unroll
        for (int mi = 0; mi < 4; mi++)
            #pragma unroll
            for (int ni = 0; ni < 4; ni++) {
                const uint32_t* bhp = &bh4[ni >> 1][(ni & 1)*2];
                const uint32_t* blp = &bl4[ni >> 1][(ni & 1)*2];
                mma_bf16(acc[mi][ni], afh[mi], bhp);
                mma_bf16(acc[mi][ni], afh[mi], blp);
                mma_bf16(acc[mi][ni], afl[mi], bhp);
            }
        if (c + 1 < nCh) { __syncthreads(); storeS(buf ^ 1); __syncthreads(); }
    }

    #pragma unroll
    for (int mi = 0; mi < 4; mi++) {
        int row = m0 + wm + mi*16 + g;
        #pragma unroll
        for (int ni = 0; ni < 4; ni++) {
            int col = n0 + wn + ni*8 + tq*2;
            if (col < N) {
                float b0v = bias ? bias[col]     : 0.f;
                float b1v = bias ? bias[col + 1] : 0.f;
                float2 v0; v0.x = acc[mi][ni][0] + b0v; v0.y = acc[mi][ni][1] + b1v;
                float2 v1; v1.x = acc[mi][ni][2] + b0v; v1.y = acc[mi][ni][3] + b1v;
                *(float2*)(C + (size_t)row*N + col)       = v0;
                *(float2*)(C + (size_t)(row + 8)*N + col) = v1;
            }
        }
    }
}

#define SMEM_ALL (8*ASTRW*4)   // 49152 bytes

// ---------------- elementwise kernels ----------------
__global__ void gather_kernel(const float* __restrict__ x) {
    size_t idx = (size_t)blockIdx.x * blockDim.x + threadIdx.x;  // MROWS*768 exact
    size_t bt = idx / 768; int r = (int)(idx % 768);
    int s = r >> 8, d = r & 255;
    int b = (int)(bt >> 11), t = (int)(bt & 2047);
    g_xg[idx] = x[(((size_t)(b*NSC + s)*TLEN + t) << 8) + d];
}

__global__ void flip_kernel() {
    size_t idx = (size_t)blockIdx.x * blockDim.x + threadIdx.x;  // MROWS*512
    size_t bt = idx >> 9; int j = (int)(idx & 511);
    int b = (int)(bt >> 11), t = (int)(bt & 2047);
    g_hf[idx] = g_h[(((size_t)(b << 11) | (2047 - t)) << 9) | j];
}

__global__ void ln512_kernel(const float* __restrict__ in, const float* __restrict__ g,
                             const float* __restrict__ b, float* __restrict__ out) {
    int row = blockIdx.x, tid = threadIdx.x;
    const float* xr = in + (size_t)row * DM2;
    float v0 = xr[tid], v1 = xr[tid + 256];
    float mu = block_reduce(v0 + v1) * (1.f / 512.f);
    float d0 = v0 - mu, d1 = v1 - mu;
    float var = block_reduce(d0*d0 + d1*d1) * (1.f / 512.f);
    float inv = rsqrtf(var + 1e-5f);
    out[(size_t)row*DM2 + tid]       = d0 * inv * g[tid]       + b[tid];
    out[(size_t)row*DM2 + tid + 256] = d1 * inv * g[tid + 256] + b[tid + 256];
}

__global__ void conv_kernel(int dir, const float* __restrict__ cw, const float* __restrict__ cb) {
    size_t idx = (size_t)blockIdx.x * blockDim.x + threadIdx.x;  // MROWS*CCH
    size_t bt = idx / CCH; int c = (int)(idx % CCH);
    int t = (int)(bt & 2047);
    const float* zx = g_zx[dir];
    float acc = cb[c];
    #pragma unroll
    for (int j = 0; j < 4; j++) {
        int tt = t - 3 + j;
        if (tt >= 0)
            acc += cw[c*4 + j] * zx[(bt + j - 3)*(size_t)DPROJ + DIN + c];
    }
    g_xbc[dir][idx] = siluf(acc);
}

__global__ void dtda_kernel(int dir, const float* __restrict__ dtb, const float* __restrict__ Alog) {
    size_t idx = (size_t)blockIdx.x * blockDim.x + threadIdx.x;  // MROWS*NH
    size_t row = idx >> 4; int hh = (int)(idx & 15);
    float raw = g_zx[dir][row*(size_t)DPROJ + 2*DIN + 2*DS + hh] + dtb[hh];
    float dtv = (raw > 20.f) ? raw : log1pf(expf(raw));
    float dAv = expf(-expf(Alog[hh]) * dtv);
    g_dt[dir][idx] = dtv;
    g_dA[dir][idx] = dAv;
}

// ---------------- sequential SSM scan (sync-free inner loop, f32x2 packed) -------
#define GP 20
__global__ void __launch_bounds__(512) scan_kernel(
    const float* __restrict__ Dh_f, const float* __restrict__ Dh_b)
{
    int blk = blockIdx.x;
    int dir = blk >> 6;
    int bh  = blk & 63;
    int b = bh >> 4, hh = bh & 15;
    const float* __restrict__ xbc = g_xbc[dir];
    const float* __restrict__ zx  = g_zx[dir];
    const float* __restrict__ dtb = g_dt[dir];
    const float* __restrict__ dAb = g_dA[dir];
    float* __restrict__ yout = g_y[dir];
    float Dval = (dir ? Dh_b : Dh_f)[hh];

    const int tid = threadIdx.x;
    const int p  = tid >> 3;     // 0..63
    const int ng = tid & 7;      // 0..7 -> n = ng*16 .. +15

    double S2[8];
    #pragma unroll
    for (int i = 0; i < 8; i++) S2[i] = 0.0;

    __shared__ float sx[8][64], sz[8][64];
    __shared__ float sB[8][8*GP], sC[8][8*GP];
    __shared__ float sdt[8], sdA[8];
    __shared__ float sy[8][64];

    size_t rowbase = (size_t)b * TLEN;

    for (int c0 = 0; c0 < TLEN; c0 += 8) {
        __syncthreads();
        {
            int t = tid >> 6, pp = tid & 63;
            size_t r = rowbase + c0 + t;
            sx[t][pp] = xbc[r*(size_t)CCH + hh*HD + pp];
            sz[t][pp] = zx [r*(size_t)DPROJ + hh*HD + pp];
        }
        #pragma unroll
        for (int q = 0; q < 2; q++) {
            int idx = tid + q*512;
            int t = idx >> 7, n = idx & 127;
            int off = (n >> 4)*GP + (n & 15);
            size_t r = rowbase + c0 + t;
            sB[t][off] = xbc[r*(size_t)CCH + DIN + n];
            sC[t][off] = xbc[r*(size_t)CCH + DIN + DS + n];
        }
        if (tid < 8) {
            size_t r = rowbase + c0 + tid;
            sdt[tid] = dtb[r*NH + hh];
            sdA[tid] = dAb[r*NH + hh];
        }
        __syncthreads();

        #pragma unroll
        for (int t = 0; t < 8; t++) {
            float dtv = sdt[t], dAv = sdA[t];
            float coef = dtv * sx[t][p];
            double dA2, cf2, part2;
            PACK2(dA2, dAv, dAv);
            PACK2(cf2, coef, coef);
            PACK2(part2, 0.f, 0.f);
            const double* B2 = (const double*)&sB[t][ng*GP];
            const double* C2 = (const double*)&sC[t][ng*GP];
            #pragma unroll
            for (int i = 0; i < 4; i++) {
                double2 bb = *(const double2*)(B2 + 2*i);
                double2 cc = *(const double2*)(C2 + 2*i);
                double tmp;
                MUL2(tmp, bb.x, cf2);
                FMA2(S2[2*i],     dA2, S2[2*i],     tmp);
                FMA2(part2, S2[2*i],     cc.x, part2);
                MUL2(tmp, bb.y, cf2);
                FMA2(S2[2*i + 1], dA2, S2[2*i + 1], tmp);
                FMA2(part2, S2[2*i + 1], cc.y, part2);
            }
            float plo, phi;
            UNPACK2(plo, phi, part2);
            float partial = plo + phi;
            partial += __shfl_xor_sync(0xffffffffu, partial, 1);
            partial += __shfl_xor_sync(0xffffffffu, partial, 2);
            partial += __shfl_xor_sync(0xffffffffu, partial, 4);
            if (ng == 0) sy[t][p] = partial;
        }
        __syncthreads();

        {
            int t = tid >> 6, pp = tid & 63;
            float y = sy[t][pp];
            float xv = sx[t][pp];
            float zv = sz[t][pp];
            float yv = (y + Dval * xv) * siluf(zv);
            yout[(rowbase + c0 + t)*(size_t)DIN + hh*HD + pp] = yv;
        }
    }
}

__global__ void rms_kernel(float* __restrict__ Y, const float* __restrict__ w) {
    int row = blockIdx.x, tid = threadIdx.x;
    float* yr = Y + (size_t)row * DIN;
    float v[4]; float ss = 0.f;
    #pragma unroll
    for (int i = 0; i < 4; i++) { v[i] = yr[tid + i*256]; ss += v[i]*v[i]; }
    ss = block_reduce(ss);
    float inv = rsqrtf(ss * (1.f/1024.f) + 1e-5f);
    #pragma unroll
    for (int i = 0; i < 4; i++) yr[tid + i*256] = v[i] * inv * w[tid + i*256];
}

__global__ void combine_kernel() {
    size_t idx = (size_t)blockIdx.x * blockDim.x + threadIdx.x;  // MROWS*512
    size_t bt = idx >> 9; int j = (int)(idx & 511);
    int b = (int)(bt >> 11), t = (int)(bt & 2047);
    float hv = g_h[idx];
    float ob = g_od[1][(((size_t)(b << 11) | (2047 - t)) << 9) | j];
    g_u[idx] = (g_od[0][idx] + ob) * siluf(hv);
}

__global__ void lnpost_kernel(const float* __restrict__ vbuf, const float* __restrict__ g,
                              const float* __restrict__ b, float* __restrict__ outdst) {
    int row = blockIdx.x, tid = threadIdx.x;
    float x = vbuf[(size_t)row*DMODEL + tid];
    float mu = block_reduce(x) * (1.f/256.f);
    float d = x - mu;
    float var = block_reduce(d*d) * (1.f/256.f);
    float o = d * rsqrtf(var + 1e-5f) * g[tid] + b[tid] + g_xp[(size_t)row*DMODEL + tid];
    outdst[(size_t)row*DMODEL + tid] = o;
    float ss = block_reduce(o*o);
    float sc = 1.f / fmaxf(sqrtf(ss), 1e-12f);
    g_fn[(size_t)row*DMODEL + tid] = o * sc;
}

// ---------------- launcher ----------------
extern "C" void kernel_launch(void* const* d_in, const int* in_sizes, int n_in,
                              void* d_out, int out_size)
{
    const float* x       = (const float*)d_in[0];
    const float* Wp      = (const float*)d_in[1];
    const float* bp      = (const float*)d_in[2];
    const float* Wpre    = (const float*)d_in[3];
    const float* bpre    = (const float*)d_in[4];
    const float* lnpre_g = (const float*)d_in[5];
    const float* lnpre_b = (const float*)d_in[6];
    const float* Wpost   = (const float*)d_in[7];
    const float* bpost   = (const float*)d_in[8];
    const float* lnpost_g= (const float*)d_in[9];
    const float* lnpost_b= (const float*)d_in[10];
    const float* Win[2]   = {(const float*)d_in[11], (const float*)d_in[19]};
    const float* convw[2] = {(const float*)d_in[12], (const float*)d_in[20]};
    const float* convb[2] = {(const float*)d_in[13], (const float*)d_in[21]};
    const float* dtb[2]   = {(const float*)d_in[14], (const float*)d_in[22]};
    const float* Alog[2]  = {(const float*)d_in[15], (const float*)d_in[23]};
    const float* Dh[2]    = {(const float*)d_in[16], (const float*)d_in[24]};
    const float* normw[2] = {(const float*)d_in[17], (const float*)d_in[25]};
    const float* Wout[2]  = {(const float*)d_in[18], (const float*)d_in[26]};

    static bool attr_done = false;
    if (!attr_done) {
        cudaFuncSetAttribute(tgemmT, cudaFuncAttributeMaxDynamicSharedMemorySize, SMEM_ALL);
        attr_done = true;
    }

    float *xg, *xp, *pre, *h, *hf, *zxb, *yb, *odb, *u, *v, *fn, *wt;
    cudaGetSymbolAddress((void**)&xg,  g_xg);
    cudaGetSymbolAddress((void**)&xp,  g_xp);
    cudaGetSymbolAddress((void**)&pre, g_pre);
    cudaGetSymbolAddress((void**)&h,   g_h);
    cudaGetSymbolAddress((void**)&hf,  g_hf);
    cudaGetSymbolAddress((void**)&zxb, g_zx);
    cudaGetSymbolAddress((void**)&yb,  g_y);
    cudaGetSymbolAddress((void**)&odb, g_od);
    cudaGetSymbolAddress((void**)&u,   g_u);
    cudaGetSymbolAddress((void**)&v,   g_v);
    cudaGetSymbolAddress((void**)&fn,  g_fn);
    cudaGetSymbolAddress((void**)&wt,  g_wt);
    float* zx0 = zxb;
    float* zx1 = zxb + (size_t)MROWS*DPROJ;
    float* y0  = yb;
    float* y1  = yb + (size_t)MROWS*DIN;
    float* od0 = odb;
    float* od1 = odb + (size_t)MROWS*DM2;

    float* wpT    = wt + OFF_WPT;
    float* wpreT  = wt + OFF_WPRET;
    float* winT0  = wt + OFF_WINT0;
    float* winT1  = wt + OFF_WINT1;
    float* woutT0 = wt + OFF_WOUTT0;
    float* woutT1 = wt + OFF_WOUTT1;
    float* wpostT = wt + OFF_WPOSTT;

    float* out  = (float*)d_out;
    float* attn = out + (size_t)MROWS*DMODEL;

    dim3 tb(32, 8);
    // 0. transpose all weights to [N][K] row-major
    transpose_kernel<<<dim3(DMODEL/32, 768/32),   tb>>>(Wp,      wpT,    768,  DMODEL);
    transpose_kernel<<<dim3(DM2/32,    DMODEL/32),tb>>>(Wpre,    wpreT,  DMODEL, DM2);
    transpose_kernel<<<dim3((DPROJ+31)/32, DM2/32), tb>>>(Win[0], winT0, DM2, DPROJ);
    transpose_kernel<<<dim3((DPROJ+31)/32, DM2/32), tb>>>(Win[1], winT1, DM2, DPROJ);
    transpose_kernel<<<dim3(DM2/32,    DIN/32),  tb>>>(Wout[0],  woutT0, DIN,  DM2);
    transpose_kernel<<<dim3(DM2/32,    DIN/32),  tb>>>(Wout[1],  woutT1, DIN,  DM2);
    transpose_kernel<<<dim3(DMODEL/32, DM2/32),  tb>>>(Wpost,    wpostT, DM2,  DMODEL);

    // 1. gather + input projection
    gather_kernel<<<MROWS*768/256, 256>>>(x);
    tgemmT<<<dim3(DMODEL/128, MROWS/128), 256, SMEM_ALL>>>(xg, wpT,   bp,   xp,  MROWS, DMODEL, 768, 0,0,0);
    // 2. pre-layernorm
    tgemmT<<<dim3(DM2/128,    MROWS/128), 256, SMEM_ALL>>>(xp, wpreT, bpre, pre, MROWS, DM2,    DMODEL, 0,0,0);
    ln512_kernel<<<MROWS, 256>>>(pre, lnpre_g, lnpre_b, h);
    flip_kernel<<<MROWS*DM2/256, 256>>>();
    // 3. mamba in-projections (both directions)
    tgemmT<<<dim3((DPROJ+127)/128, MROWS/128), 256, SMEM_ALL>>>(h,  winT0, nullptr, zx0, MROWS, DPROJ, DM2, 0,0,0);
    tgemmT<<<dim3((DPROJ+127)/128, MROWS/128), 256, SMEM_ALL>>>(hf, winT1, nullptr, zx1, MROWS, DPROJ, DM2, 0,0,0);
    // 4. conv + dt/dA
    for (int dir = 0; dir < 2; dir++) {
        conv_kernel<<<MROWS*CCH/256, 256>>>(dir, convw[dir], convb[dir]);
        dtda_kernel<<<MROWS*NH/256, 256>>>(dir, dtb[dir], Alog[dir]);
    }
    // 5. both scans concurrently
    scan_kernel<<<128, 512>>>(Dh[0], Dh[1]);
    // 6. RMS-norm + out-projections
    rms_kernel<<<MROWS, 256>>>(y0, normw[0]);
    rms_kernel<<<MROWS, 256>>>(y1, normw[1]);
    tgemmT<<<dim3(DM2/128, MROWS/128), 256, SMEM_ALL>>>(y0, woutT0, nullptr, od0, MROWS, DM2, DIN, 0,0,0);
    tgemmT<<<dim3(DM2/128, MROWS/128), 256, SMEM_ALL>>>(y1, woutT1, nullptr, od1, MROWS, DM2, DIN, 0,0,0);
    // 7. gated combine + post projection + post-LN(+residual) + fn
    combine_kernel<<<MROWS*DM2/256, 256>>>();
    tgemmT<<<dim3(DMODEL/128, MROWS/128), 256, SMEM_ALL>>>(u, wpostT, bpost, v, MROWS, DMODEL, DM2, 0,0,0);
    lnpost_kernel<<<MROWS, 256>>>(v, lnpost_g, lnpost_b, out);
    // 8. attn = fn @ fn^T per batch
    tgemmT<<<dim3(TLEN/128, TLEN/128, BATCH), 256, SMEM_ALL>>>(
        fn, fn, nullptr, attn, TLEN, TLEN, DMODEL,
        (size_t)TLEN*DMODEL, (size_t)TLEN*DMODEL, (size_t)TLEN*TLEN);
}